// round 8
// baseline (speedup 1.0000x reference)
#include <cuda_runtime.h>
#include <cstdint>
#include <math.h>

#define BB 512
#define GRID (BB / 2)             // 256 CTAs, 2 batches each
#define MM 4096
#define DD 64
#define CC 256
#define NT 256                    // 8 warps
#define NW (NT / 32)
#define ROWPAD 17                 // float4 per padded row
#define NBUF 5                    // ring stages per warp
#define SROWS 8                   // rows per stage (2 KB)
#define STG4 (SROWS * ROWPAD)     // 136 float4 per stage
#define WBUF4 (NBUF * STG4)       // 680 float4 per warp
#define NSTG 64                   // stages per warp per batch
#define ROWS_PER_WARP 512
#define RPT (MM / NT)             // 16
#define EPSF 1e-8f
#define LOG2E 1.442695040888963f

// smem floats: 8 warps * WBUF4 * 4 + SA + misc  (~105 KB -> 2 CTAs/SM)
#define SMEM_FLOATS (8 * WBUF4 * 4 + MM + CC + DD + 8 + 6 + 6)
#define SMEM_BYTES (SMEM_FLOATS * 4)

// ---- software exp2 / log2 (FMA-pipe transcendentals) ----
__device__ __forceinline__ float fast_exp2(float y) {
    y = fmaxf(y, -250.0f);
    float t = y + 12582912.0f;
    int   ni = __float_as_int(t) - 0x4B400000;
    float f = y - (t - 12582912.0f);
    float p = 1.52527338e-5f;
    p = fmaf(p, f, 1.54035304e-4f);
    p = fmaf(p, f, 1.33335581e-3f);
    p = fmaf(p, f, 9.61812911e-3f);
    p = fmaf(p, f, 5.55041087e-2f);
    p = fmaf(p, f, 2.40226507e-1f);
    p = fmaf(p, f, 6.93147181e-1f);
    p = fmaf(p, f, 1.0f);
    int n1 = ni >> 1;
    int n2 = ni - n1;
    float s1 = __int_as_float((n1 + 127) << 23);
    float s2 = __int_as_float((n2 + 127) << 23);
    return p * s1 * s2;
}

__device__ __forceinline__ float fast_log2(float x) {
    int ix = __float_as_int(x);
    int e = ((ix >> 23) & 0xff) - 127;
    float m = __int_as_float((ix & 0x007fffff) | 0x3f800000);
    if (m > 1.41421356f) { m *= 0.5f; e += 1; }
    float s = __fdividef(m - 1.0f, m + 1.0f);
    float s2 = s * s;
    float p = 0.111111111f;
    p = fmaf(p, s2, 0.142857143f);
    p = fmaf(p, s2, 0.2f);
    p = fmaf(p, s2, 0.333333333f);
    p = fmaf(p, s2, 1.0f);
    float lnm = 2.0f * s * p;
    return (float)e + lnm * LOG2E;
}

__device__ __forceinline__ float fast_exp(float z) { return fast_exp2(z * LOG2E); }
__device__ __forceinline__ float fast_pow(float x, float g) { return fast_exp2(g * fast_log2(x)); }

__device__ __forceinline__ float blockReduceSum(float v, float* sh) {
    int lane = threadIdx.x & 31, wid = threadIdx.x >> 5;
    #pragma unroll
    for (int o = 16; o; o >>= 1) v += __shfl_xor_sync(0xffffffffu, v, o);
    __syncthreads();
    if (lane == 0) sh[wid] = v;
    __syncthreads();
    if (wid == 0) {
        float x = (lane < NW) ? sh[lane] : 0.0f;
        #pragma unroll
        for (int o = NW / 2; o; o >>= 1) x += __shfl_xor_sync(0xffffffffu, x, o);
        if (lane == 0) sh[0] = x;
    }
    __syncthreads();
    return sh[0];
}

__device__ __forceinline__ float blockReduceMax(float v, float* sh) {
    int lane = threadIdx.x & 31, wid = threadIdx.x >> 5;
    #pragma unroll
    for (int o = 16; o; o >>= 1) v = fmaxf(v, __shfl_xor_sync(0xffffffffu, v, o));
    __syncthreads();
    if (lane == 0) sh[wid] = v;
    __syncthreads();
    if (wid == 0) {
        float x = (lane < NW) ? sh[lane] : -INFINITY;
        #pragma unroll
        for (int o = NW / 2; o; o >>= 1) x = fmaxf(x, __shfl_xor_sync(0xffffffffu, x, o));
        if (lane == 0) sh[0] = x;
    }
    __syncthreads();
    return sh[0];
}

// one 2 KB stage: 128 float4, 4 cp.async per lane, fully coalesced
__device__ __forceinline__ void prefetch_stage(const float4* gsrc,
                                               uint32_t dst_u32, int lane) {
    #pragma unroll
    for (int k = 0; k < 4; k++) {
        int lin = k * 32 + lane;
        int r = lin >> 4, c = lin & 15;
        uint32_t dst = dst_u32 + (uint32_t)(r * ROWPAD + c) * 16u;
        asm volatile("cp.async.cg.shared.global [%0], [%1], 16;\n"
                     :: "r"(dst), "l"(gsrc + lin) : "memory");
    }
    asm volatile("cp.async.commit_group;\n" ::: "memory");
}

__global__ __launch_bounds__(NT)
void ntm_head_kernel(
    const float* __restrict__ memory,     // (B, M, D)
    const float* __restrict__ cstate,     // (B, C)
    const float* __restrict__ prevw,      // (B, M)
    const float* __restrict__ Wk,         // (C, D)
    const float* __restrict__ Wb,
    const float* __restrict__ bb,
    const float* __restrict__ Wgate,
    const float* __restrict__ bgate,
    const float* __restrict__ Ws,
    const float* __restrict__ bs,
    const float* __restrict__ Wg,
    const float* __restrict__ bg,
    float* __restrict__ out)              // (B, M)
{
    extern __shared__ float smem[];
    float4* buf     = reinterpret_cast<float4*>(smem);       // 8 * WBUF4
    float*  SA      = smem + 8 * WBUF4 * 4;                  // MM
    float*  sh_cs   = SA + MM;                               // CC
    float*  sh_qn   = sh_cs + CC;                            // DD
    float*  sh_red  = sh_qn + DD;                            // 8
    float*  sh_scal = sh_red + 8;                            // 6
    float*  sh_par  = sh_scal + 6;                           // 6

    const int tid  = threadIdx.x;
    const int lane = tid & 31;
    const int wid  = tid >> 5;

    const uint32_t buf_u32  = (uint32_t)__cvta_generic_to_shared(buf);
    const float4*  mem4     = reinterpret_cast<const float4*>(memory);
    const float4*  wbuf     = buf + wid * WBUF4;
    const uint32_t wbuf_u32 = buf_u32 + (uint32_t)(wid * WBUF4) * 16u;

    // global stage g (0..127): batch = blockIdx.x + (g>>6)*GRID, rows w*512+(g&63)*8
    // src pointer for stage g:
    //   mem4 + (b*MM + wid*512 + (g&63)*8) * 16
    // prefetch stages 0..3 immediately
    #pragma unroll
    for (int g = 0; g < 4; g++) {
        const float4* src = mem4 + ((size_t)blockIdx.x * MM
                                    + wid * ROWS_PER_WARP + g * SROWS) * (DD / 4);
        prefetch_stage(src, wbuf_u32 + (uint32_t)(g * STG4) * 16u, lane);
    }

    for (int bi = 0; bi < 2; bi++) {
        const int b = blockIdx.x + bi * GRID;

        // ================= preamble =================
        sh_cs[tid] = cstate[(size_t)b * CC + tid];
        __syncthreads();

        if (tid < DD) {
            float acc = 0.0f;
            #pragma unroll 8
            for (int c = 0; c < CC; c++) acc = fmaf(sh_cs[c], Wk[c * DD + tid], acc);
            sh_qn[tid] = acc;
        }
        if (wid >= 2) {
            int s = wid - 2;
            float acc = 0.0f;
            if (s < 3) {
                const float* W = (s == 0) ? Wb : (s == 1) ? Wgate : Wg;
                for (int c = lane; c < CC; c += 32) acc = fmaf(sh_cs[c], W[c], acc);
            } else {
                int col = s - 3;
                for (int c = lane; c < CC; c += 32) acc = fmaf(sh_cs[c], Ws[c * 3 + col], acc);
            }
            #pragma unroll
            for (int o = 16; o; o >>= 1) acc += __shfl_xor_sync(0xffffffffu, acc, o);
            if (lane == 0) sh_scal[s] = acc;
        }
        __syncthreads();

        if (wid == 0) {
            float a = sh_qn[lane], c = sh_qn[lane + 32];
            float v = a * a + c * c;
            #pragma unroll
            for (int o = 16; o; o >>= 1) v += __shfl_xor_sync(0xffffffffu, v, o);
            float inv = 1.0f / (sqrtf(v) + EPSF);
            sh_qn[lane]      = a * inv;
            sh_qn[lane + 32] = c * inv;
        }
        if (tid == 32) {
            sh_par[0] = log1pf(__expf(sh_scal[0] + bb[0])) + 1.0f;            // beta
            sh_par[1] = 1.0f / (1.0f + __expf(-(sh_scal[1] + bgate[0])));     // gate
            sh_par[2] = log1pf(__expf(sh_scal[2] + bg[0])) + 1.0f;            // gamma
            float a0 = sh_scal[3] + bs[0];
            float a1 = sh_scal[4] + bs[1];
            float a2 = sh_scal[5] + bs[2];
            float mx = fmaxf(a0, fmaxf(a1, a2));
            float e0 = __expf(a0 - mx), e1 = __expf(a1 - mx), e2 = __expf(a2 - mx);
            float inv = 1.0f / (e0 + e1 + e2);
            sh_par[3] = e0 * inv; sh_par[4] = e1 * inv; sh_par[5] = e2 * inv;
        }
        __syncthreads();

        // per-lane query segment: lane (lane&3) covers float4s [(lane&3)*4, +4)
        float4 qreg[4];
        {
            const float4* qn4 = reinterpret_cast<const float4*>(sh_qn);
            #pragma unroll
            for (int j = 0; j < 4; j++) qreg[j] = qn4[(lane & 3) * 4 + j];
        }

        // ================= per-warp stream: no block barriers =================
        int slot = (bi == 0) ? 0 : (64 % NBUF);       // g mod 5 at s=0
        float* SAw = SA + wid * ROWS_PER_WARP;

        for (int s = 0; s < NSTG; s++) {
            const int g = bi * 64 + s;

            // wait until stage g's group (this warp's) is complete
            if (bi == 0 || s < 61) {
                asm volatile("cp.async.wait_group 3;\n" ::: "memory");
            } else if (s == 61) {
                asm volatile("cp.async.wait_group 2;\n" ::: "memory");
            } else if (s == 62) {
                asm volatile("cp.async.wait_group 1;\n" ::: "memory");
            } else {
                asm volatile("cp.async.wait_group 0;\n" ::: "memory");
            }

            // compute: 8 rows, 4 lanes per row, 4 consecutive float4 per lane
            const float4* rowp = wbuf + slot * STG4
                               + (lane >> 2) * ROWPAD + (lane & 3) * 4;
            float dot = 0.0f, ss = 0.0f;
            #pragma unroll
            for (int j = 0; j < 4; j++) {
                float4 v = rowp[j];
                float4 q = qreg[j];
                dot = fmaf(v.x, q.x, dot); dot = fmaf(v.y, q.y, dot);
                dot = fmaf(v.z, q.z, dot); dot = fmaf(v.w, q.w, dot);
                ss  = fmaf(v.x, v.x, ss);  ss  = fmaf(v.y, v.y, ss);
                ss  = fmaf(v.z, v.z, ss);  ss  = fmaf(v.w, v.w, ss);
            }
            dot += __shfl_xor_sync(0xffffffffu, dot, 1);
            ss  += __shfl_xor_sync(0xffffffffu, ss,  1);
            dot += __shfl_xor_sync(0xffffffffu, dot, 2);
            ss  += __shfl_xor_sync(0xffffffffu, ss,  2);
            if ((lane & 3) == 0)
                SAw[s * SROWS + (lane >> 2)] = dot * rsqrtf(ss);

            // prefetch stage g+4 (continues seamlessly into next batch)
            const int gp = g + 4;
            if (gp < 128) {
                const size_t bp = (size_t)blockIdx.x + (size_t)(gp >> 6) * GRID;
                const float4* src = mem4 + (bp * MM + wid * ROWS_PER_WARP
                                            + (gp & 63) * SROWS) * (DD / 4);
                int pslot = slot + 4; if (pslot >= NBUF) pslot -= NBUF;
                prefetch_stage(src, wbuf_u32 + (uint32_t)(pslot * STG4) * 16u, lane);
            }
            if (++slot == NBUF) slot = 0;
        }
        __syncthreads();   // all warps' sims in SA

        // ================= epilogue (b1 DMA already in flight) =================
        const float beta = sh_par[0];
        float lmax = -INFINITY;
        #pragma unroll
        for (int k = 0; k < RPT; k++) lmax = fmaxf(lmax, SA[tid + k * NT]);
        const float smax = blockReduceMax(lmax, sh_red) * beta;

        float lsum = 0.0f;
        #pragma unroll
        for (int k = 0; k < RPT; k++) {
            int m = tid + k * NT;
            float e = fast_exp(fmaf(beta, SA[m], -smax));
            SA[m] = e;
            lsum += e;
        }
        const float invsum = 1.0f / blockReduceSum(lsum, sh_red);

        const float gate = sh_par[1], gate1 = 1.0f - sh_par[1];
        const float* pw = prevw + (size_t)b * MM;
        #pragma unroll
        for (int k = 0; k < RPT; k++) {
            int m = tid + k * NT;
            SA[m] = fmaf(gate, SA[m] * invsum, gate1 * pw[m]);
        }
        __syncthreads();

        const float gamma = sh_par[2];
        const float s0 = sh_par[3], s1 = sh_par[4], s2 = sh_par[5];
        float p[RPT];
        float psum = 0.0f;
        #pragma unroll
        for (int k = 0; k < RPT; k++) {
            int m  = tid + k * NT;
            int ml = (m == 0)      ? MM - 1 : m - 1;
            int mr = (m == MM - 1) ? 0      : m + 1;
            float sv = SA[ml] * s0 + SA[m] * s1 + SA[mr] * s2;
            p[k] = fast_pow(sv + EPSF, gamma);
            psum += p[k];
        }
        psum = blockReduceSum(psum, sh_red);   // internal barrier: SA reads done
        const float invp = 1.0f / (psum + EPSF);

        float* ob = out + (size_t)b * MM;
        #pragma unroll
        for (int k = 0; k < RPT; k++) {
            int m = tid + k * NT;
            ob[m] = p[k] * invp;
        }
        __syncthreads();   // SA / sh_* reusable for next batch
    }
}

extern "C" void kernel_launch(void* const* d_in, const int* in_sizes, int n_in,
                              void* d_out, int out_size) {
    const float* memory = (const float*)d_in[0];
    const float* cstate = (const float*)d_in[1];
    const float* prevw  = (const float*)d_in[2];
    const float* Wk     = (const float*)d_in[3];
    const float* Wb     = (const float*)d_in[4];
    const float* bb     = (const float*)d_in[5];
    const float* Wgate  = (const float*)d_in[6];
    const float* bgate  = (const float*)d_in[7];
    const float* Ws     = (const float*)d_in[8];
    const float* bs     = (const float*)d_in[9];
    const float* Wg     = (const float*)d_in[10];
    const float* bg     = (const float*)d_in[11];
    float* out = (float*)d_out;

    static int smem_set = 0;
    if (!smem_set) {
        cudaFuncSetAttribute(ntm_head_kernel,
                             cudaFuncAttributeMaxDynamicSharedMemorySize,
                             SMEM_BYTES);
        smem_set = 1;
    }

    ntm_head_kernel<<<GRID, NT, SMEM_BYTES>>>(memory, cstate, prevw,
                                              Wk, Wb, bb, Wgate, bgate,
                                              Ws, bs, Wg, bg, out);
}

// round 9
// speedup vs baseline: 1.0753x; 1.0753x over previous
#include <cuda_runtime.h>
#include <cstdint>
#include <math.h>

#define BB 512
#define GRID (BB / 2)             // 256 CTAs, 2 batches each
#define MM 4096
#define DD 64
#define CC 256
#define NT 256                    // 8 warps
#define NW (NT / 32)
#define TILE 64                   // rows per tile (16 KB data)
#define NTILES 64                 // tiles per batch
#define TOTTILES 128              // tiles across both batches
#define ROWPAD 17                 // float4 per padded row
#define NBUF 5                    // ring slots
#define STG4 (TILE * ROWPAD)      // 1088 float4 per slot
#define RPT (MM / NT)             // 16
#define EPSF 1e-8f
#define LOG2E 1.442695040888963f

// smem floats: NBUF slots + SA + misc  (~104.8 KB -> 2 CTAs/SM)
#define SMEM_FLOATS (NBUF * STG4 * 4 + MM + CC + DD + 8 + 6 + 6)
#define SMEM_BYTES (SMEM_FLOATS * 4)

// ---- software exp2 / log2 (FMA-pipe transcendentals) ----
__device__ __forceinline__ float fast_exp2(float y) {
    y = fmaxf(y, -250.0f);
    float t = y + 12582912.0f;
    int   ni = __float_as_int(t) - 0x4B400000;
    float f = y - (t - 12582912.0f);
    float p = 1.52527338e-5f;
    p = fmaf(p, f, 1.54035304e-4f);
    p = fmaf(p, f, 1.33335581e-3f);
    p = fmaf(p, f, 9.61812911e-3f);
    p = fmaf(p, f, 5.55041087e-2f);
    p = fmaf(p, f, 2.40226507e-1f);
    p = fmaf(p, f, 6.93147181e-1f);
    p = fmaf(p, f, 1.0f);
    int n1 = ni >> 1;
    int n2 = ni - n1;
    float s1 = __int_as_float((n1 + 127) << 23);
    float s2 = __int_as_float((n2 + 127) << 23);
    return p * s1 * s2;
}

__device__ __forceinline__ float fast_log2(float x) {
    int ix = __float_as_int(x);
    int e = ((ix >> 23) & 0xff) - 127;
    float m = __int_as_float((ix & 0x007fffff) | 0x3f800000);
    if (m > 1.41421356f) { m *= 0.5f; e += 1; }
    float s = __fdividef(m - 1.0f, m + 1.0f);
    float s2 = s * s;
    float p = 0.111111111f;
    p = fmaf(p, s2, 0.142857143f);
    p = fmaf(p, s2, 0.2f);
    p = fmaf(p, s2, 0.333333333f);
    p = fmaf(p, s2, 1.0f);
    float lnm = 2.0f * s * p;
    return (float)e + lnm * LOG2E;
}

__device__ __forceinline__ float fast_exp(float z) { return fast_exp2(z * LOG2E); }
__device__ __forceinline__ float fast_pow(float x, float g) { return fast_exp2(g * fast_log2(x)); }

__device__ __forceinline__ float blockReduceSum(float v, float* sh) {
    int lane = threadIdx.x & 31, wid = threadIdx.x >> 5;
    #pragma unroll
    for (int o = 16; o; o >>= 1) v += __shfl_xor_sync(0xffffffffu, v, o);
    __syncthreads();
    if (lane == 0) sh[wid] = v;
    __syncthreads();
    if (wid == 0) {
        float x = (lane < NW) ? sh[lane] : 0.0f;
        #pragma unroll
        for (int o = NW / 2; o; o >>= 1) x += __shfl_xor_sync(0xffffffffu, x, o);
        if (lane == 0) sh[0] = x;
    }
    __syncthreads();
    return sh[0];
}

__device__ __forceinline__ float blockReduceMax(float v, float* sh) {
    int lane = threadIdx.x & 31, wid = threadIdx.x >> 5;
    #pragma unroll
    for (int o = 16; o; o >>= 1) v = fmaxf(v, __shfl_xor_sync(0xffffffffu, v, o));
    __syncthreads();
    if (lane == 0) sh[wid] = v;
    __syncthreads();
    if (wid == 0) {
        float x = (lane < NW) ? sh[lane] : -INFINITY;
        #pragma unroll
        for (int o = NW / 2; o; o >>= 1) x = fmaxf(x, __shfl_xor_sync(0xffffffffu, x, o));
        if (lane == 0) sh[0] = x;
    }
    __syncthreads();
    return sh[0];
}

// one 16 KB tile: 1024 float4, 4 cp.async per thread, coalesced
__device__ __forceinline__ void prefetch_tile(const float4* gsrc,
                                              uint32_t dst_u32, int tid) {
    #pragma unroll
    for (int k = 0; k < 4; k++) {
        int lin = tid + k * NT;             // 0..1023
        int r = lin >> 4, c = lin & 15;
        uint32_t dst = dst_u32 + (uint32_t)(r * ROWPAD + c) * 16u;
        asm volatile("cp.async.cg.shared.global [%0], [%1], 16;\n"
                     :: "r"(dst), "l"(gsrc + lin) : "memory");
    }
    asm volatile("cp.async.commit_group;\n" ::: "memory");
}

// src pointer for global tile g (0..127)
__device__ __forceinline__ const float4* tile_src(const float4* mem4, int cta, int g) {
    size_t b = (size_t)cta + (size_t)(g >> 6) * GRID;
    return mem4 + (b * MM + (size_t)(g & 63) * TILE) * (DD / 4);
}

__global__ __launch_bounds__(NT)
void ntm_head_kernel(
    const float* __restrict__ memory,     // (B, M, D)
    const float* __restrict__ cstate,     // (B, C)
    const float* __restrict__ prevw,      // (B, M)
    const float* __restrict__ Wk,         // (C, D)
    const float* __restrict__ Wb,
    const float* __restrict__ bb,
    const float* __restrict__ Wgate,
    const float* __restrict__ bgate,
    const float* __restrict__ Ws,
    const float* __restrict__ bs,
    const float* __restrict__ Wg,
    const float* __restrict__ bg,
    float* __restrict__ out)              // (B, M)
{
    extern __shared__ float smem[];
    float4* buf     = reinterpret_cast<float4*>(smem);       // NBUF * STG4
    float*  SA      = smem + NBUF * STG4 * 4;                 // MM
    float*  sh_cs   = SA + MM;                                // CC
    float*  sh_qn   = sh_cs + CC;                             // DD
    float*  sh_red  = sh_qn + DD;                             // 8
    float*  sh_scal = sh_red + 8;                             // 6
    float*  sh_par  = sh_scal + 6;                            // 6

    const int tid  = threadIdx.x;
    const int lane = tid & 31;
    const int wid  = tid >> 5;

    const uint32_t buf_u32 = (uint32_t)__cvta_generic_to_shared(buf);
    const float4*  mem4    = reinterpret_cast<const float4*>(memory);

    // ---- prologue: issue tiles 0..3 into slots 0..3 ----
    #pragma unroll
    for (int g = 0; g < 4; g++)
        prefetch_tile(tile_src(mem4, blockIdx.x, g),
                      buf_u32 + (uint32_t)(g * STG4) * 16u, tid);

    for (int bi = 0; bi < 2; bi++) {
        const int b = blockIdx.x + bi * GRID;

        // ================= preamble (under in-flight DMA) =================
        sh_cs[tid] = cstate[(size_t)b * CC + tid];
        __syncthreads();

        if (tid < DD) {
            float acc = 0.0f;
            #pragma unroll 8
            for (int c = 0; c < CC; c++) acc = fmaf(sh_cs[c], Wk[c * DD + tid], acc);
            sh_qn[tid] = acc;
        }
        if (wid >= 2) {
            int s = wid - 2;
            float acc = 0.0f;
            if (s < 3) {
                const float* W = (s == 0) ? Wb : (s == 1) ? Wgate : Wg;
                for (int c = lane; c < CC; c += 32) acc = fmaf(sh_cs[c], W[c], acc);
            } else {
                int col = s - 3;
                for (int c = lane; c < CC; c += 32) acc = fmaf(sh_cs[c], Ws[c * 3 + col], acc);
            }
            #pragma unroll
            for (int o = 16; o; o >>= 1) acc += __shfl_xor_sync(0xffffffffu, acc, o);
            if (lane == 0) sh_scal[s] = acc;
        }
        __syncthreads();

        if (wid == 0) {
            float a = sh_qn[lane], c = sh_qn[lane + 32];
            float v = a * a + c * c;
            #pragma unroll
            for (int o = 16; o; o >>= 1) v += __shfl_xor_sync(0xffffffffu, v, o);
            float inv = 1.0f / (sqrtf(v) + EPSF);
            sh_qn[lane]      = a * inv;
            sh_qn[lane + 32] = c * inv;
        }
        if (tid == 32) {
            sh_par[0] = log1pf(__expf(sh_scal[0] + bb[0])) + 1.0f;            // beta
            sh_par[1] = 1.0f / (1.0f + __expf(-(sh_scal[1] + bgate[0])));     // gate
            sh_par[2] = log1pf(__expf(sh_scal[2] + bg[0])) + 1.0f;            // gamma
            float a0 = sh_scal[3] + bs[0];
            float a1 = sh_scal[4] + bs[1];
            float a2 = sh_scal[5] + bs[2];
            float mx = fmaxf(a0, fmaxf(a1, a2));
            float e0 = __expf(a0 - mx), e1 = __expf(a1 - mx), e2 = __expf(a2 - mx);
            float inv = 1.0f / (e0 + e1 + e2);
            sh_par[3] = e0 * inv; sh_par[4] = e1 * inv; sh_par[5] = e2 * inv;
        }
        __syncthreads();

        // per-lane query quarter: lane&3 covers float4s [(lane&3)*4, +4)
        float4 qreg[4];
        {
            const float4* qn4 = reinterpret_cast<const float4*>(sh_qn);
            #pragma unroll
            for (int j = 0; j < 4; j++) qreg[j] = qn4[(lane & 3) * 4 + j];
        }

        // ================= stream loop: depth-4 ring, 1 barrier/iter ========
        const int row4 = (tid >> 2) * ROWPAD + (tid & 3) * 4;  // this thread's slice
        for (int s = 0; s < NTILES; s++) {
            const int g = bi * NTILES + s;

            // complete group g (issued = min(g+4, 128) groups so far)
            const int rem = TOTTILES - 1 - g;   // groups after g
            if (rem >= 3)      asm volatile("cp.async.wait_group 3;\n" ::: "memory");
            else if (rem == 2) asm volatile("cp.async.wait_group 2;\n" ::: "memory");
            else if (rem == 1) asm volatile("cp.async.wait_group 1;\n" ::: "memory");
            else               asm volatile("cp.async.wait_group 0;\n" ::: "memory");
            __syncthreads();   // tile g visible; tile g-1's compute finished everywhere

            // refill: tile g+4 into slot (g+4)%NBUF == slot of tile g-1 (safe)
            if (g + 4 < TOTTILES) {
                int pslot = (g + 4) % NBUF;
                prefetch_tile(tile_src(mem4, blockIdx.x, g + 4),
                              buf_u32 + (uint32_t)(pslot * STG4) * 16u, tid);
            }

            // compute tile g from slot g%NBUF: 4 lanes per row
            const float4* rowp = buf + (g % NBUF) * STG4 + row4;
            float dot = 0.0f, ss = 0.0f;
            #pragma unroll
            for (int j = 0; j < 4; j++) {
                float4 v = rowp[j];
                float4 q = qreg[j];
                dot = fmaf(v.x, q.x, dot); dot = fmaf(v.y, q.y, dot);
                dot = fmaf(v.z, q.z, dot); dot = fmaf(v.w, q.w, dot);
                ss  = fmaf(v.x, v.x, ss);  ss  = fmaf(v.y, v.y, ss);
                ss  = fmaf(v.z, v.z, ss);  ss  = fmaf(v.w, v.w, ss);
            }
            dot += __shfl_xor_sync(0xffffffffu, dot, 1);
            ss  += __shfl_xor_sync(0xffffffffu, ss,  1);
            dot += __shfl_xor_sync(0xffffffffu, dot, 2);
            ss  += __shfl_xor_sync(0xffffffffu, ss,  2);
            if ((lane & 3) == 0)
                SA[s * TILE + (tid >> 2)] = dot * rsqrtf(ss);
        }
        __syncthreads();   // all sims in SA

        // ================= epilogue (batch-1 tiles still streaming) =========
        const float beta = sh_par[0];
        float lmax = -INFINITY;
        #pragma unroll
        for (int k = 0; k < RPT; k++) lmax = fmaxf(lmax, SA[tid + k * NT]);
        const float smax = blockReduceMax(lmax, sh_red) * beta;

        float lsum = 0.0f;
        #pragma unroll
        for (int k = 0; k < RPT; k++) {
            int m = tid + k * NT;
            float e = fast_exp(fmaf(beta, SA[m], -smax));
            SA[m] = e;
            lsum += e;
        }
        const float invsum = 1.0f / blockReduceSum(lsum, sh_red);

        const float gate = sh_par[1], gate1 = 1.0f - sh_par[1];
        const float* pw = prevw + (size_t)b * MM;
        #pragma unroll
        for (int k = 0; k < RPT; k++) {
            int m = tid + k * NT;
            SA[m] = fmaf(gate, SA[m] * invsum, gate1 * pw[m]);
        }
        __syncthreads();

        const float gamma = sh_par[2];
        const float s0 = sh_par[3], s1 = sh_par[4], s2 = sh_par[5];
        float p[RPT];
        float psum = 0.0f;
        #pragma unroll
        for (int k = 0; k < RPT; k++) {
            int m  = tid + k * NT;
            int ml = (m == 0)      ? MM - 1 : m - 1;
            int mr = (m == MM - 1) ? 0      : m + 1;
            float sv = SA[ml] * s0 + SA[m] * s1 + SA[mr] * s2;
            p[k] = fast_pow(sv + EPSF, gamma);
            psum += p[k];
        }
        psum = blockReduceSum(psum, sh_red);   // barrier: SA reads done
        const float invp = 1.0f / (psum + EPSF);

        float* ob = out + (size_t)b * MM;
        #pragma unroll
        for (int k = 0; k < RPT; k++) {
            int m = tid + k * NT;
            ob[m] = p[k] * invp;
        }
        __syncthreads();   // SA / sh_* reusable
    }
}

extern "C" void kernel_launch(void* const* d_in, const int* in_sizes, int n_in,
                              void* d_out, int out_size) {
    const float* memory = (const float*)d_in[0];
    const float* cstate = (const float*)d_in[1];
    const float* prevw  = (const float*)d_in[2];
    const float* Wk     = (const float*)d_in[3];
    const float* Wb     = (const float*)d_in[4];
    const float* bb     = (const float*)d_in[5];
    const float* Wgate  = (const float*)d_in[6];
    const float* bgate  = (const float*)d_in[7];
    const float* Ws     = (const float*)d_in[8];
    const float* bs     = (const float*)d_in[9];
    const float* Wg     = (const float*)d_in[10];
    const float* bg     = (const float*)d_in[11];
    float* out = (float*)d_out;

    static int smem_set = 0;
    if (!smem_set) {
        cudaFuncSetAttribute(ntm_head_kernel,
                             cudaFuncAttributeMaxDynamicSharedMemorySize,
                             SMEM_BYTES);
        smem_set = 1;
    }

    ntm_head_kernel<<<GRID, NT, SMEM_BYTES>>>(memory, cstate, prevw,
                                              Wk, Wb, bb, Wgate, bgate,
                                              Ws, bs, Wg, bg, out);
}

// round 10
// speedup vs baseline: 1.1195x; 1.0411x over previous
#include <cuda_runtime.h>
#include <cstdint>
#include <math.h>

#define BB 512
#define GRID (BB / 2)             // 256 CTAs, 2 batches each
#define MM 4096
#define DD 64
#define CC 256
#define NT 256                    // 8 warps
#define NW (NT / 32)
#define TILE 64                   // rows per tile
#define TILE_BYTES 16384          // 64 rows * 256 B, contiguous in gmem
#define TILE4 1024                // float4 per tile
#define NTILES 64                 // tiles per batch
#define TOTTILES 128
#define NBUF 5                    // ring slots
#define RPT (MM / NT)             // 16
#define EPSF 1e-8f
#define LOG2E 1.442695040888963f

// smem floats: 16 (mbar block) + NBUF*TILE4*4 + SA + misc  (~99.7 KB -> 2 CTAs/SM)
#define SMEM_FLOATS (16 + NBUF * TILE4 * 4 + MM + CC + DD + 8 + 6 + 6)
#define SMEM_BYTES (SMEM_FLOATS * 4)

// ---- software exp2 / log2 (FMA-pipe transcendentals) ----
__device__ __forceinline__ float fast_exp2(float y) {
    y = fmaxf(y, -250.0f);
    float t = y + 12582912.0f;
    int   ni = __float_as_int(t) - 0x4B400000;
    float f = y - (t - 12582912.0f);
    float p = 1.52527338e-5f;
    p = fmaf(p, f, 1.54035304e-4f);
    p = fmaf(p, f, 1.33335581e-3f);
    p = fmaf(p, f, 9.61812911e-3f);
    p = fmaf(p, f, 5.55041087e-2f);
    p = fmaf(p, f, 2.40226507e-1f);
    p = fmaf(p, f, 6.93147181e-1f);
    p = fmaf(p, f, 1.0f);
    int n1 = ni >> 1;
    int n2 = ni - n1;
    float s1 = __int_as_float((n1 + 127) << 23);
    float s2 = __int_as_float((n2 + 127) << 23);
    return p * s1 * s2;
}

__device__ __forceinline__ float fast_log2(float x) {
    int ix = __float_as_int(x);
    int e = ((ix >> 23) & 0xff) - 127;
    float m = __int_as_float((ix & 0x007fffff) | 0x3f800000);
    if (m > 1.41421356f) { m *= 0.5f; e += 1; }
    float s = __fdividef(m - 1.0f, m + 1.0f);
    float s2 = s * s;
    float p = 0.111111111f;
    p = fmaf(p, s2, 0.142857143f);
    p = fmaf(p, s2, 0.2f);
    p = fmaf(p, s2, 0.333333333f);
    p = fmaf(p, s2, 1.0f);
    float lnm = 2.0f * s * p;
    return (float)e + lnm * LOG2E;
}

__device__ __forceinline__ float fast_exp(float z) { return fast_exp2(z * LOG2E); }
__device__ __forceinline__ float fast_pow(float x, float g) { return fast_exp2(g * fast_log2(x)); }

__device__ __forceinline__ float blockReduceSum(float v, float* sh) {
    int lane = threadIdx.x & 31, wid = threadIdx.x >> 5;
    #pragma unroll
    for (int o = 16; o; o >>= 1) v += __shfl_xor_sync(0xffffffffu, v, o);
    __syncthreads();
    if (lane == 0) sh[wid] = v;
    __syncthreads();
    if (wid == 0) {
        float x = (lane < NW) ? sh[lane] : 0.0f;
        #pragma unroll
        for (int o = NW / 2; o; o >>= 1) x += __shfl_xor_sync(0xffffffffu, x, o);
        if (lane == 0) sh[0] = x;
    }
    __syncthreads();
    return sh[0];
}

__device__ __forceinline__ float blockReduceMax(float v, float* sh) {
    int lane = threadIdx.x & 31, wid = threadIdx.x >> 5;
    #pragma unroll
    for (int o = 16; o; o >>= 1) v = fmaxf(v, __shfl_xor_sync(0xffffffffu, v, o));
    __syncthreads();
    if (lane == 0) sh[wid] = v;
    __syncthreads();
    if (wid == 0) {
        float x = (lane < NW) ? sh[lane] : -INFINITY;
        #pragma unroll
        for (int o = NW / 2; o; o >>= 1) x = fmaxf(x, __shfl_xor_sync(0xffffffffu, x, o));
        if (lane == 0) sh[0] = x;
    }
    __syncthreads();
    return sh[0];
}

// acquire-parity wait on an smem mbarrier
__device__ __forceinline__ void mbar_wait(uint32_t mbar, uint32_t parity) {
    asm volatile(
        "{\n\t"
        ".reg .pred P;\n\t"
        "WAIT_%=:\n\t"
        "mbarrier.try_wait.parity.acquire.cta.shared::cta.b64 P, [%0], %1, 0x989680;\n\t"
        "@!P bra WAIT_%=;\n\t"
        "}"
        :: "r"(mbar), "r"(parity) : "memory");
}

// single-thread: arm slot barrier and launch one 16 KB TMA bulk copy
__device__ __forceinline__ void issue_tile(const float* memory, int cta, int g,
                                           uint32_t buf_u32, uint32_t mbar_u32) {
    int slot = g % NBUF;
    size_t b = (size_t)cta + (size_t)(g >> 6) * GRID;
    const float* src = memory + (b * MM + (size_t)(g & 63) * TILE) * DD;
    uint32_t dst = buf_u32 + (uint32_t)slot * TILE_BYTES;
    uint32_t mb  = mbar_u32 + (uint32_t)(slot * 8);
    asm volatile("mbarrier.arrive.expect_tx.shared::cta.b64 _, [%0], %1;"
                 :: "r"(mb), "r"(TILE_BYTES) : "memory");
    asm volatile("cp.async.bulk.shared::cta.global.mbarrier::complete_tx::bytes "
                 "[%0], [%1], %2, [%3];"
                 :: "r"(dst), "l"(src), "r"(TILE_BYTES), "r"(mb) : "memory");
}

__global__ __launch_bounds__(NT)
void ntm_head_kernel(
    const float* __restrict__ memory,     // (B, M, D)
    const float* __restrict__ cstate,     // (B, C)
    const float* __restrict__ prevw,      // (B, M)
    const float* __restrict__ Wk,         // (C, D)
    const float* __restrict__ Wb,
    const float* __restrict__ bb,
    const float* __restrict__ Wgate,
    const float* __restrict__ bgate,
    const float* __restrict__ Ws,
    const float* __restrict__ bs,
    const float* __restrict__ Wg,
    const float* __restrict__ bg,
    float* __restrict__ out)              // (B, M)
{
    extern __shared__ float smem[];
    // [0..16): mbarriers (5 x 8B, padded)
    float4* buf     = reinterpret_cast<float4*>(smem + 16);  // NBUF * TILE4, unpadded
    float*  SA      = smem + 16 + NBUF * TILE4 * 4;           // MM
    float*  sh_cs   = SA + MM;                                // CC
    float*  sh_qn   = sh_cs + CC;                             // DD
    float*  sh_red  = sh_qn + DD;                             // 8
    float*  sh_scal = sh_red + 8;                             // 6
    float*  sh_par  = sh_scal + 6;                            // 6

    const int tid  = threadIdx.x;
    const int lane = tid & 31;
    const int wid  = tid >> 5;

    const uint32_t mbar_u32 = (uint32_t)__cvta_generic_to_shared(smem);
    const uint32_t buf_u32  = (uint32_t)__cvta_generic_to_shared(buf);

    // ---- init mbarriers, then launch tiles 0..3 ----
    if (tid == 0) {
        #pragma unroll
        for (int s = 0; s < NBUF; s++)
            asm volatile("mbarrier.init.shared::cta.b64 [%0], 1;"
                         :: "r"(mbar_u32 + (uint32_t)(s * 8)) : "memory");
    }
    __syncthreads();
    if (tid == 0) {
        #pragma unroll
        for (int g = 0; g < 4; g++)
            issue_tile(memory, blockIdx.x, g, buf_u32, mbar_u32);
    }

    for (int bi = 0; bi < 2; bi++) {
        const int b = blockIdx.x + bi * GRID;

        // ================= preamble (under in-flight DMA) =================
        sh_cs[tid] = cstate[(size_t)b * CC + tid];
        __syncthreads();

        if (tid < DD) {
            float acc = 0.0f;
            #pragma unroll 8
            for (int c = 0; c < CC; c++) acc = fmaf(sh_cs[c], Wk[c * DD + tid], acc);
            sh_qn[tid] = acc;
        }
        if (wid >= 2) {
            int s = wid - 2;
            float acc = 0.0f;
            if (s < 3) {
                const float* W = (s == 0) ? Wb : (s == 1) ? Wgate : Wg;
                for (int c = lane; c < CC; c += 32) acc = fmaf(sh_cs[c], W[c], acc);
            } else {
                int col = s - 3;
                for (int c = lane; c < CC; c += 32) acc = fmaf(sh_cs[c], Ws[c * 3 + col], acc);
            }
            #pragma unroll
            for (int o = 16; o; o >>= 1) acc += __shfl_xor_sync(0xffffffffu, acc, o);
            if (lane == 0) sh_scal[s] = acc;
        }
        __syncthreads();

        if (wid == 0) {
            float a = sh_qn[lane], c = sh_qn[lane + 32];
            float v = a * a + c * c;
            #pragma unroll
            for (int o = 16; o; o >>= 1) v += __shfl_xor_sync(0xffffffffu, v, o);
            float inv = 1.0f / (sqrtf(v) + EPSF);
            sh_qn[lane]      = a * inv;
            sh_qn[lane + 32] = c * inv;
        }
        if (tid == 32) {
            sh_par[0] = log1pf(__expf(sh_scal[0] + bb[0])) + 1.0f;            // beta
            sh_par[1] = 1.0f / (1.0f + __expf(-(sh_scal[1] + bgate[0])));     // gate
            sh_par[2] = log1pf(__expf(sh_scal[2] + bg[0])) + 1.0f;            // gamma
            float a0 = sh_scal[3] + bs[0];
            float a1 = sh_scal[4] + bs[1];
            float a2 = sh_scal[5] + bs[2];
            float mx = fmaxf(a0, fmaxf(a1, a2));
            float e0 = __expf(a0 - mx), e1 = __expf(a1 - mx), e2 = __expf(a2 - mx);
            float inv = 1.0f / (e0 + e1 + e2);
            sh_par[3] = e0 * inv; sh_par[4] = e1 * inv; sh_par[5] = e2 * inv;
        }
        __syncthreads();

        // query segment for 8-lanes-per-row layout: lane li covers float4s li, li+8
        const int li   = tid & 7;          // lane within row
        const int rrow = tid >> 3;         // 0..31 (row within half-tile)
        float4 q0, q1;
        {
            const float4* qn4 = reinterpret_cast<const float4*>(sh_qn);
            q0 = qn4[li];
            q1 = qn4[li + 8];
        }

        // ================= stream loop: TMA ring, depth-4 =================
        for (int s = 0; s < NTILES; s++) {
            const int g = bi * NTILES + s;

            mbar_wait(mbar_u32 + (uint32_t)((g % NBUF) * 8), (uint32_t)((g / NBUF) & 1));
            __syncthreads();   // tile g visible; everyone finished compute of g-1

            // refill slot (g+4)%NBUF == slot of tile g-1 (freed by the barrier)
            if (g + 4 < TOTTILES && tid == 0)
                issue_tile(memory, blockIdx.x, g + 4, buf_u32, mbar_u32);

            // compute tile g: 8 lanes per row, stride-8 float4 -> conflict-free
            const float4* base = buf + (size_t)(g % NBUF) * TILE4;
            #pragma unroll
            for (int p = 0; p < 2; p++) {
                const int row = rrow + 32 * p;
                const float4* rp = base + row * 16 + li;
                float4 v0 = rp[0];
                float4 v1 = rp[8];
                float dot = v0.x * q0.x, ss = v0.x * v0.x;
                dot = fmaf(v0.y, q0.y, dot); ss = fmaf(v0.y, v0.y, ss);
                dot = fmaf(v0.z, q0.z, dot); ss = fmaf(v0.z, v0.z, ss);
                dot = fmaf(v0.w, q0.w, dot); ss = fmaf(v0.w, v0.w, ss);
                dot = fmaf(v1.x, q1.x, dot); ss = fmaf(v1.x, v1.x, ss);
                dot = fmaf(v1.y, q1.y, dot); ss = fmaf(v1.y, v1.y, ss);
                dot = fmaf(v1.z, q1.z, dot); ss = fmaf(v1.z, v1.z, ss);
                dot = fmaf(v1.w, q1.w, dot); ss = fmaf(v1.w, v1.w, ss);
                #pragma unroll
                for (int o = 1; o < 8; o <<= 1) {
                    dot += __shfl_xor_sync(0xffffffffu, dot, o);
                    ss  += __shfl_xor_sync(0xffffffffu, ss,  o);
                }
                if (li == 0)
                    SA[s * TILE + row] = dot * rsqrtf(ss);
            }
        }
        __syncthreads();   // all sims in SA

        // ================= epilogue (batch-1 tiles still streaming) =========
        const float beta = sh_par[0];
        float lmax = -INFINITY;
        #pragma unroll
        for (int k = 0; k < RPT; k++) lmax = fmaxf(lmax, SA[tid + k * NT]);
        const float smax = blockReduceMax(lmax, sh_red) * beta;

        float lsum = 0.0f;
        #pragma unroll
        for (int k = 0; k < RPT; k++) {
            int m = tid + k * NT;
            float e = fast_exp(fmaf(beta, SA[m], -smax));
            SA[m] = e;
            lsum += e;
        }
        const float invsum = 1.0f / blockReduceSum(lsum, sh_red);

        const float gate = sh_par[1], gate1 = 1.0f - sh_par[1];
        const float* pw = prevw + (size_t)b * MM;
        #pragma unroll
        for (int k = 0; k < RPT; k++) {
            int m = tid + k * NT;
            SA[m] = fmaf(gate, SA[m] * invsum, gate1 * pw[m]);
        }
        __syncthreads();

        const float gamma = sh_par[2];
        const float s0 = sh_par[3], s1 = sh_par[4], s2 = sh_par[5];
        float p[RPT];
        float psum = 0.0f;
        #pragma unroll
        for (int k = 0; k < RPT; k++) {
            int m  = tid + k * NT;
            int ml = (m == 0)      ? MM - 1 : m - 1;
            int mr = (m == MM - 1) ? 0      : m + 1;
            float sv = SA[ml] * s0 + SA[m] * s1 + SA[mr] * s2;
            p[k] = fast_pow(sv + EPSF, gamma);
            psum += p[k];
        }
        psum = blockReduceSum(psum, sh_red);   // barrier: SA reads done
        const float invp = 1.0f / (psum + EPSF);

        float* ob = out + (size_t)b * MM;
        #pragma unroll
        for (int k = 0; k < RPT; k++) {
            int m = tid + k * NT;
            ob[m] = p[k] * invp;
        }
        __syncthreads();   // SA / sh_* reusable
    }
}

extern "C" void kernel_launch(void* const* d_in, const int* in_sizes, int n_in,
                              void* d_out, int out_size) {
    const float* memory = (const float*)d_in[0];
    const float* cstate = (const float*)d_in[1];
    const float* prevw  = (const float*)d_in[2];
    const float* Wk     = (const float*)d_in[3];
    const float* Wb     = (const float*)d_in[4];
    const float* bb     = (const float*)d_in[5];
    const float* Wgate  = (const float*)d_in[6];
    const float* bgate  = (const float*)d_in[7];
    const float* Ws     = (const float*)d_in[8];
    const float* bs     = (const float*)d_in[9];
    const float* Wg     = (const float*)d_in[10];
    const float* bg     = (const float*)d_in[11];
    float* out = (float*)d_out;

    static int smem_set = 0;
    if (!smem_set) {
        cudaFuncSetAttribute(ntm_head_kernel,
                             cudaFuncAttributeMaxDynamicSharedMemorySize,
                             SMEM_BYTES);
        smem_set = 1;
    }

    ntm_head_kernel<<<GRID, NT, SMEM_BYTES>>>(memory, cstate, prevw,
                                              Wk, Wb, bb, Wgate, bgate,
                                              Ws, bs, Wg, bg, out);
}

// round 11
// speedup vs baseline: 1.2702x; 1.1346x over previous
#include <cuda_runtime.h>
#include <cstdint>
#include <math.h>

#define BB 512
#define MM 4096
#define DD 64
#define CC 256
#define NT 256                    // 8 warps
#define NW (NT / 32)
#define TILE 32                   // rows per tile
#define TILE_BYTES 8192           // 32 rows * 256 B, contiguous in gmem
#define TILE4 512                 // float4 per tile
#define NTILES 128                // tiles per batch
#define NBUF 4                    // ring slots
#define DEPTH 3                   // tiles in flight
#define RPT (MM / NT)             // 16
#define EPSF 1e-8f
#define LOG2E 1.442695040888963f

// smem floats: 8 (mbar block, 4x8B) + NBUF*TILE4*4 + SA + misc (~49.5 KB -> 4 CTAs/SM)
#define SMEM_FLOATS (8 + NBUF * TILE4 * 4 + MM + CC + DD + 8 + 6 + 6)
#define SMEM_BYTES (SMEM_FLOATS * 4)

// ---- software exp2 / log2 (FMA-pipe transcendentals) ----
__device__ __forceinline__ float fast_exp2(float y) {
    y = fmaxf(y, -250.0f);
    float t = y + 12582912.0f;
    int   ni = __float_as_int(t) - 0x4B400000;
    float f = y - (t - 12582912.0f);
    float p = 1.52527338e-5f;
    p = fmaf(p, f, 1.54035304e-4f);
    p = fmaf(p, f, 1.33335581e-3f);
    p = fmaf(p, f, 9.61812911e-3f);
    p = fmaf(p, f, 5.55041087e-2f);
    p = fmaf(p, f, 2.40226507e-1f);
    p = fmaf(p, f, 6.93147181e-1f);
    p = fmaf(p, f, 1.0f);
    int n1 = ni >> 1;
    int n2 = ni - n1;
    float s1 = __int_as_float((n1 + 127) << 23);
    float s2 = __int_as_float((n2 + 127) << 23);
    return p * s1 * s2;
}

__device__ __forceinline__ float fast_log2(float x) {
    int ix = __float_as_int(x);
    int e = ((ix >> 23) & 0xff) - 127;
    float m = __int_as_float((ix & 0x007fffff) | 0x3f800000);
    if (m > 1.41421356f) { m *= 0.5f; e += 1; }
    float s = __fdividef(m - 1.0f, m + 1.0f);
    float s2 = s * s;
    float p = 0.111111111f;
    p = fmaf(p, s2, 0.142857143f);
    p = fmaf(p, s2, 0.2f);
    p = fmaf(p, s2, 0.333333333f);
    p = fmaf(p, s2, 1.0f);
    float lnm = 2.0f * s * p;
    return (float)e + lnm * LOG2E;
}

__device__ __forceinline__ float fast_exp(float z) { return fast_exp2(z * LOG2E); }
__device__ __forceinline__ float fast_pow(float x, float g) { return fast_exp2(g * fast_log2(x)); }

__device__ __forceinline__ float blockReduceSum(float v, float* sh) {
    int lane = threadIdx.x & 31, wid = threadIdx.x >> 5;
    #pragma unroll
    for (int o = 16; o; o >>= 1) v += __shfl_xor_sync(0xffffffffu, v, o);
    __syncthreads();
    if (lane == 0) sh[wid] = v;
    __syncthreads();
    if (wid == 0) {
        float x = (lane < NW) ? sh[lane] : 0.0f;
        #pragma unroll
        for (int o = NW / 2; o; o >>= 1) x += __shfl_xor_sync(0xffffffffu, x, o);
        if (lane == 0) sh[0] = x;
    }
    __syncthreads();
    return sh[0];
}

__device__ __forceinline__ float blockReduceMax(float v, float* sh) {
    int lane = threadIdx.x & 31, wid = threadIdx.x >> 5;
    #pragma unroll
    for (int o = 16; o; o >>= 1) v = fmaxf(v, __shfl_xor_sync(0xffffffffu, v, o));
    __syncthreads();
    if (lane == 0) sh[wid] = v;
    __syncthreads();
    if (wid == 0) {
        float x = (lane < NW) ? sh[lane] : -INFINITY;
        #pragma unroll
        for (int o = NW / 2; o; o >>= 1) x = fmaxf(x, __shfl_xor_sync(0xffffffffu, x, o));
        if (lane == 0) sh[0] = x;
    }
    __syncthreads();
    return sh[0];
}

// acquire-parity wait on an smem mbarrier
__device__ __forceinline__ void mbar_wait(uint32_t mbar, uint32_t parity) {
    asm volatile(
        "{\n\t"
        ".reg .pred P;\n\t"
        "WAIT_%=:\n\t"
        "mbarrier.try_wait.parity.acquire.cta.shared::cta.b64 P, [%0], %1, 0x989680;\n\t"
        "@!P bra WAIT_%=;\n\t"
        "}"
        :: "r"(mbar), "r"(parity) : "memory");
}

// single-thread: arm slot barrier and launch one 8 KB TMA bulk copy
__device__ __forceinline__ void issue_tile(const float* batch_base, int g,
                                           uint32_t buf_u32, uint32_t mbar_u32) {
    int slot = g & (NBUF - 1);
    const float* src = batch_base + (size_t)g * TILE * DD;
    uint32_t dst = buf_u32 + (uint32_t)slot * TILE_BYTES;
    uint32_t mb  = mbar_u32 + (uint32_t)(slot * 8);
    asm volatile("mbarrier.arrive.expect_tx.shared::cta.b64 _, [%0], %1;"
                 :: "r"(mb), "r"(TILE_BYTES) : "memory");
    asm volatile("cp.async.bulk.shared::cta.global.mbarrier::complete_tx::bytes "
                 "[%0], [%1], %2, [%3];"
                 :: "r"(dst), "l"(src), "r"(TILE_BYTES), "r"(mb) : "memory");
}

__global__ __launch_bounds__(NT, 4)
void ntm_head_kernel(
    const float* __restrict__ memory,     // (B, M, D)
    const float* __restrict__ cstate,     // (B, C)
    const float* __restrict__ prevw,      // (B, M)
    const float* __restrict__ Wk,         // (C, D)
    const float* __restrict__ Wb,
    const float* __restrict__ bb,
    const float* __restrict__ Wgate,
    const float* __restrict__ bgate,
    const float* __restrict__ Ws,
    const float* __restrict__ bs,
    const float* __restrict__ Wg,
    const float* __restrict__ bg,
    float* __restrict__ out)              // (B, M)
{
    extern __shared__ float smem[];
    // [0..8): mbarriers (4 x 8B)
    float4* buf     = reinterpret_cast<float4*>(smem + 8);   // NBUF * TILE4
    float*  SA      = smem + 8 + NBUF * TILE4 * 4;           // MM
    float*  sh_cs   = SA + MM;                               // CC
    float*  sh_qn   = sh_cs + CC;                            // DD
    float*  sh_red  = sh_qn + DD;                            // 8
    float*  sh_scal = sh_red + 8;                            // 6
    float*  sh_par  = sh_scal + 6;                           // 6

    const int tid  = threadIdx.x;
    const int lane = tid & 31;
    const int wid  = tid >> 5;
    const int b    = blockIdx.x;

    const uint32_t mbar_u32 = (uint32_t)__cvta_generic_to_shared(smem);
    const uint32_t buf_u32  = (uint32_t)__cvta_generic_to_shared(buf);
    const float* batch_base = memory + (size_t)b * MM * DD;

    // ---- init mbarriers, launch tiles 0..DEPTH-1 ----
    if (tid == 0) {
        #pragma unroll
        for (int s = 0; s < NBUF; s++)
            asm volatile("mbarrier.init.shared::cta.b64 [%0], 1;"
                         :: "r"(mbar_u32 + (uint32_t)(s * 8)) : "memory");
    }
    __syncthreads();
    if (tid == 0) {
        #pragma unroll
        for (int g = 0; g < DEPTH; g++)
            issue_tile(batch_base, g, buf_u32, mbar_u32);
    }

    // ================= preamble (under in-flight DMA) =================
    sh_cs[tid] = cstate[(size_t)b * CC + tid];
    __syncthreads();

    if (tid < DD) {
        float acc = 0.0f;
        #pragma unroll 8
        for (int c = 0; c < CC; c++) acc = fmaf(sh_cs[c], Wk[c * DD + tid], acc);
        sh_qn[tid] = acc;
    }
    if (wid >= 2) {
        int s = wid - 2;
        float acc = 0.0f;
        if (s < 3) {
            const float* W = (s == 0) ? Wb : (s == 1) ? Wgate : Wg;
            for (int c = lane; c < CC; c += 32) acc = fmaf(sh_cs[c], W[c], acc);
        } else {
            int col = s - 3;
            for (int c = lane; c < CC; c += 32) acc = fmaf(sh_cs[c], Ws[c * 3 + col], acc);
        }
        #pragma unroll
        for (int o = 16; o; o >>= 1) acc += __shfl_xor_sync(0xffffffffu, acc, o);
        if (lane == 0) sh_scal[s] = acc;
    }
    __syncthreads();

    if (wid == 0) {
        float a = sh_qn[lane], c = sh_qn[lane + 32];
        float v = a * a + c * c;
        #pragma unroll
        for (int o = 16; o; o >>= 1) v += __shfl_xor_sync(0xffffffffu, v, o);
        float inv = 1.0f / (sqrtf(v) + EPSF);
        sh_qn[lane]      = a * inv;
        sh_qn[lane + 32] = c * inv;
    }
    if (tid == 32) {
        sh_par[0] = log1pf(__expf(sh_scal[0] + bb[0])) + 1.0f;            // beta
        sh_par[1] = 1.0f / (1.0f + __expf(-(sh_scal[1] + bgate[0])));     // gate
        sh_par[2] = log1pf(__expf(sh_scal[2] + bg[0])) + 1.0f;            // gamma
        float a0 = sh_scal[3] + bs[0];
        float a1 = sh_scal[4] + bs[1];
        float a2 = sh_scal[5] + bs[2];
        float mx = fmaxf(a0, fmaxf(a1, a2));
        float e0 = __expf(a0 - mx), e1 = __expf(a1 - mx), e2 = __expf(a2 - mx);
        float inv = 1.0f / (e0 + e1 + e2);
        sh_par[3] = e0 * inv; sh_par[4] = e1 * inv; sh_par[5] = e2 * inv;
    }
    __syncthreads();

    // query segment: 8 lanes per row, lane li covers float4s li and li+8
    const int li   = tid & 7;
    const int row  = tid >> 3;          // 0..31
    float4 q0, q1;
    {
        const float4* qn4 = reinterpret_cast<const float4*>(sh_qn);
        q0 = qn4[li];
        q1 = qn4[li + 8];
    }

    // ================= stream loop: TMA ring, depth-3, 4 streams/SM ========
    for (int g = 0; g < NTILES; g++) {
        mbar_wait(mbar_u32 + (uint32_t)((g & (NBUF - 1)) * 8),
                  (uint32_t)((g >> 2) & 1));
        __syncthreads();   // tile g visible; compute of g-1 done block-wide

        // refill slot (g+3)&3 == slot of g-1 (freed by the barrier above)
        if (g + DEPTH < NTILES && tid == 0)
            issue_tile(batch_base, g + DEPTH, buf_u32, mbar_u32);

        // compute tile g: 8 lanes/row, 2x LDS.128, conflict-free
        const float4* rp = buf + (size_t)(g & (NBUF - 1)) * TILE4 + row * 16 + li;
        float4 v0 = rp[0];
        float4 v1 = rp[8];
        float dot = v0.x * q0.x, ss = v0.x * v0.x;
        dot = fmaf(v0.y, q0.y, dot); ss = fmaf(v0.y, v0.y, ss);
        dot = fmaf(v0.z, q0.z, dot); ss = fmaf(v0.z, v0.z, ss);
        dot = fmaf(v0.w, q0.w, dot); ss = fmaf(v0.w, v0.w, ss);
        dot = fmaf(v1.x, q1.x, dot); ss = fmaf(v1.x, v1.x, ss);
        dot = fmaf(v1.y, q1.y, dot); ss = fmaf(v1.y, v1.y, ss);
        dot = fmaf(v1.z, q1.z, dot); ss = fmaf(v1.z, v1.z, ss);
        dot = fmaf(v1.w, q1.w, dot); ss = fmaf(v1.w, v1.w, ss);
        #pragma unroll
        for (int o = 1; o < 8; o <<= 1) {
            dot += __shfl_xor_sync(0xffffffffu, dot, o);
            ss  += __shfl_xor_sync(0xffffffffu, ss,  o);
        }
        if (li == 0)
            SA[g * TILE + row] = dot * rsqrtf(ss);
    }
    __syncthreads();   // all sims in SA

    // ================= epilogue =================
    const float beta = sh_par[0];
    float lmax = -INFINITY;
    #pragma unroll
    for (int k = 0; k < RPT; k++) lmax = fmaxf(lmax, SA[tid + k * NT]);
    const float smax = blockReduceMax(lmax, sh_red) * beta;

    float lsum = 0.0f;
    #pragma unroll
    for (int k = 0; k < RPT; k++) {
        int m = tid + k * NT;
        float e = fast_exp(fmaf(beta, SA[m], -smax));
        SA[m] = e;
        lsum += e;
    }
    const float invsum = 1.0f / blockReduceSum(lsum, sh_red);

    const float gate = sh_par[1], gate1 = 1.0f - sh_par[1];
    const float* pw = prevw + (size_t)b * MM;
    #pragma unroll
    for (int k = 0; k < RPT; k++) {
        int m = tid + k * NT;
        SA[m] = fmaf(gate, SA[m] * invsum, gate1 * pw[m]);
    }
    __syncthreads();

    const float gamma = sh_par[2];
    const float s0 = sh_par[3], s1 = sh_par[4], s2 = sh_par[5];
    float p[RPT];
    float psum = 0.0f;
    #pragma unroll
    for (int k = 0; k < RPT; k++) {
        int m  = tid + k * NT;
        int ml = (m == 0)      ? MM - 1 : m - 1;
        int mr = (m == MM - 1) ? 0      : m + 1;
        float sv = SA[ml] * s0 + SA[m] * s1 + SA[mr] * s2;
        p[k] = fast_pow(sv + EPSF, gamma);
        psum += p[k];
    }
    psum = blockReduceSum(psum, sh_red);
    const float invp = 1.0f / (psum + EPSF);

    float* ob = out + (size_t)b * MM;
    #pragma unroll
    for (int k = 0; k < RPT; k++) {
        int m = tid + k * NT;
        ob[m] = p[k] * invp;
    }
}

extern "C" void kernel_launch(void* const* d_in, const int* in_sizes, int n_in,
                              void* d_out, int out_size) {
    const float* memory = (const float*)d_in[0];
    const float* cstate = (const float*)d_in[1];
    const float* prevw  = (const float*)d_in[2];
    const float* Wk     = (const float*)d_in[3];
    const float* Wb     = (const float*)d_in[4];
    const float* bb     = (const float*)d_in[5];
    const float* Wgate  = (const float*)d_in[6];
    const float* bgate  = (const float*)d_in[7];
    const float* Ws     = (const float*)d_in[8];
    const float* bs     = (const float*)d_in[9];
    const float* Wg     = (const float*)d_in[10];
    const float* bg     = (const float*)d_in[11];
    float* out = (float*)d_out;

    static int smem_set = 0;
    if (!smem_set) {
        cudaFuncSetAttribute(ntm_head_kernel,
                             cudaFuncAttributeMaxDynamicSharedMemorySize,
                             SMEM_BYTES);
        smem_set = 1;
    }

    ntm_head_kernel<<<BB, NT, SMEM_BYTES>>>(memory, cstate, prevw,
                                            Wk, Wb, bb, Wgate, bgate,
                                            Ws, bs, Wg, bg, out);
}